// round 10
// baseline (speedup 1.0000x reference)
#include <cuda_runtime.h>

// ---------------------------------------------------------------------------
// Problem constants
// ---------------------------------------------------------------------------
#define NN 20000          // N_NODES
#define NE 320000         // N_EDGES
#define H_DIM 128
#define K_CF 162          // NUM_SEM + MAXPP + FS
#define FG_DIM 128
#define ETN_DIM 4
#define EW_LD 260         // 2*H + ETN
#define EW_ITER_STRIDE (128*260)

#define ENC_NEG_INF 0x007FFFFFu   // encf(-inf)

static __device__ __forceinline__ unsigned encf(float f) {
    unsigned u = __float_as_uint(f);
    return (u & 0x80000000u) ? ~u : (u | 0x80000000u);
}
static __device__ __forceinline__ float decf(unsigned e) {
    unsigned u = (e & 0x80000000u) ? (e & 0x7FFFFFFFu) : ~e;
    return __uint_as_float(u);
}
static __device__ __forceinline__ float leaky(float x) {
    return fmaxf(x, 0.01f * x);
}

// ---------------------------------------------------------------------------
// Scratch (static __device__ arrays: no allocations allowed)
// ---------------------------------------------------------------------------
__device__ float   g_cf0[NN * H_DIM];
__device__ float   g_cf1[NN * H_DIM];
__device__ float   g_A  [NN * H_DIM];
__device__ float   g_B  [NN * H_DIM];
__device__ int     g_deg[NN];
__device__ int     g_off[NN + 1];
__device__ int     g_cursor[NN];
__device__ int2    g_sorted[NE];
__device__ unsigned g_p0[H_DIM], g_p1[H_DIM], g_p2[H_DIM];
__device__ unsigned g_gcg[H_DIM], g_gskip[H_DIM];

// ---------------------------------------------------------------------------
// Init: zero degrees, set channel-max accumulators to enc(-inf)
// ---------------------------------------------------------------------------
__global__ void init_k(int* deg, unsigned* p0, unsigned* p1, unsigned* p2,
                       unsigned* gcg, unsigned* gskip) {
    int i = blockIdx.x * blockDim.x + threadIdx.x;
    if (i < NN) deg[i] = 0;
    if (i < H_DIM) {
        p0[i] = ENC_NEG_INF; p1[i] = ENC_NEG_INF; p2[i] = ENC_NEG_INF;
        gcg[i] = ENC_NEG_INF; gskip[i] = ENC_NEG_INF;
    }
}

// ---------------------------------------------------------------------------
// Generic GEMM: C[m][n] = (sum_k X[m][k]*W[n][k] + bias[n]) * (EXISTS? ex[m]:1)
//   X: M x K (row stride ldx), W: 128 x K (row stride ldw), C: M x 128.
//   Optional store, optional per-channel max (encoded uint atomics).
// Tile: BM=64, BN=128, BK=16, 128 threads, 8x8 register tile per thread.
// ---------------------------------------------------------------------------
#define BM 64
#define BN 128
#define BKK 16

template<bool EXISTS, bool STORE, bool CMAX>
__global__ __launch_bounds__(128)
void gemm_k(const float* __restrict__ X, int ldx,
            const float* __restrict__ W, int ldw,
            const float* __restrict__ bias,
            const float* __restrict__ ex,
            float* __restrict__ C,
            unsigned* __restrict__ cmax,
            int M, int K) {
    __shared__ float As[BKK][BM + 4];
    __shared__ float Bs[BKK][BN + 4];
    __shared__ unsigned smax[BN];

    const int tid = threadIdx.x;
    const int tr = tid >> 4;   // 0..7
    const int tc = tid & 15;   // 0..15
    const int m0 = blockIdx.x * BM;

    if (CMAX) smax[tid] = ENC_NEG_INF;   // blockDim == 128 == BN

    float acc[8][8];
#pragma unroll
    for (int i = 0; i < 8; i++)
#pragma unroll
        for (int j = 0; j < 8; j++) acc[i][j] = 0.f;

    for (int k0 = 0; k0 < K; k0 += BKK) {
        // Load A tile (64x16), transposed into As[k][m]
#pragma unroll
        for (int i = 0; i < 8; i++) {
            int idx = tid + 128 * i;
            int m = idx >> 4, k = idx & 15;
            int gm = m0 + m, gk = k0 + k;
            As[k][m] = (gm < M && gk < K) ? X[(size_t)gm * ldx + gk] : 0.f;
        }
        // Load B tile (128 rows of W, 16 k) into Bs[k][n]
#pragma unroll
        for (int i = 0; i < 16; i++) {
            int idx = tid + 128 * i;
            int n = idx >> 4, k = idx & 15;
            int gk = k0 + k;
            Bs[k][n] = (gk < K) ? W[(size_t)n * ldw + gk] : 0.f;
        }
        __syncthreads();

#pragma unroll
        for (int kk = 0; kk < BKK; kk++) {
            float4 a0 = *(const float4*)&As[kk][tr * 8];
            float4 a1 = *(const float4*)&As[kk][tr * 8 + 4];
            float4 b0 = *(const float4*)&Bs[kk][tc * 8];
            float4 b1 = *(const float4*)&Bs[kk][tc * 8 + 4];
            float a[8] = {a0.x, a0.y, a0.z, a0.w, a1.x, a1.y, a1.z, a1.w};
            float b[8] = {b0.x, b0.y, b0.z, b0.w, b1.x, b1.y, b1.z, b1.w};
#pragma unroll
            for (int i = 0; i < 8; i++)
#pragma unroll
                for (int j = 0; j < 8; j++)
                    acc[i][j] = fmaf(a[i], b[j], acc[i][j]);
        }
        __syncthreads();
    }

    // Epilogue
    float bv[8];
#pragma unroll
    for (int j = 0; j < 8; j++) bv[j] = bias ? bias[tc * 8 + j] : 0.f;

    unsigned cm[8];
#pragma unroll
    for (int j = 0; j < 8; j++) cm[j] = ENC_NEG_INF;

#pragma unroll
    for (int i = 0; i < 8; i++) {
        int gm = m0 + tr * 8 + i;
        if (gm < M) {
            float e = EXISTS ? ex[gm] : 1.f;
#pragma unroll
            for (int j = 0; j < 8; j++) {
                float v = (acc[i][j] + bv[j]) * e;
                if (STORE) C[(size_t)gm * BN + tc * 8 + j] = v;
                if (CMAX)  cm[j] = max(cm[j], encf(v));
            }
        }
    }

    if (CMAX) {
        // syncthreads in main loop guarantees smax init is visible
#pragma unroll
        for (int j = 0; j < 8; j++) atomicMax(&smax[tc * 8 + j], cm[j]);
        __syncthreads();
        atomicMax(&cmax[tid], smax[tid]);
    }
}

// ---------------------------------------------------------------------------
// CSR build: count / scan / scatter
// ---------------------------------------------------------------------------
__global__ void count_k(const int* __restrict__ ei, int* __restrict__ deg) {
    int e = blockIdx.x * blockDim.x + threadIdx.x;
    if (e < NE) atomicAdd(&deg[ei[2 * e]], 1);
}

__global__ __launch_bounds__(1024)
void scan_k(const int* __restrict__ deg, int* __restrict__ off,
            int* __restrict__ cursor) {
    __shared__ int tsum[1024];
    const int t = threadIdx.x;
    const int IT = 20;                       // 1024*20 >= 20000
    const int base = t * IT;
    int local[IT];
    int s = 0;
#pragma unroll
    for (int i = 0; i < IT; i++) {
        int idx = base + i;
        int v = (idx < NN) ? deg[idx] : 0;
        local[i] = s;
        s += v;
    }
    tsum[t] = s;
    __syncthreads();
    // Hillis-Steele inclusive scan
    for (int d = 1; d < 1024; d <<= 1) {
        int v = (t >= d) ? tsum[t - d] : 0;
        __syncthreads();
        tsum[t] += v;
        __syncthreads();
    }
    int excl = (t == 0) ? 0 : tsum[t - 1];
#pragma unroll
    for (int i = 0; i < IT; i++) {
        int idx = base + i;
        if (idx < NN) {
            int o = excl + local[i];
            off[idx] = o;
            cursor[idx] = o;
        }
    }
    if (t == 0) off[NN] = tsum[1023];
}

__global__ void scatter_k(const int* __restrict__ ei, int* __restrict__ cursor,
                          int2* __restrict__ sorted) {
    int e = blockIdx.x * blockDim.x + threadIdx.x;
    if (e < NE) {
        int f = ei[2 * e];
        int to = ei[2 * e + 1];
        int p = atomicAdd(&cursor[f], 1);
        sorted[p] = make_int2(to, e);
    }
}

// ---------------------------------------------------------------------------
// Segmented max per node (warp per node, 4 channels per lane):
//   M[h]      = max_{e: from=n} (B[to_e][h] + edge_b[h] + ef[e] . W3[h])
//   cf_new[n] = relu(A[n] + M)   (0 if degree 0)
// Also accumulates per-channel max over nodes (p_{i+1}).
// Grid must cover exactly NN warps (NN % warps_per_block == 0).
// ---------------------------------------------------------------------------
__global__ __launch_bounds__(256)
void segmax_k(const float* __restrict__ A, const float* __restrict__ Bt,
              const int2* __restrict__ sorted, const int* __restrict__ off,
              const float* __restrict__ ef,
              const float* __restrict__ Wit,   // edge_w + iter*128*260
              const float* __restrict__ bit,   // edge_b + iter*128
              float* __restrict__ cfo, unsigned* __restrict__ pmax) {
    __shared__ unsigned smax[H_DIM];
    const int tid = threadIdx.x;
    if (tid < H_DIM) smax[tid] = ENC_NEG_INF;
    __syncthreads();

    const int warp = tid >> 5, lane = tid & 31;
    const int n = blockIdx.x * (blockDim.x >> 5) + warp;   // always < NN (exact grid)
    const int c0 = lane * 4;

    float w3[4][4], bb[4];
#pragma unroll
    for (int j = 0; j < 4; j++) {
        bb[j] = bit[c0 + j];
#pragma unroll
        for (int q = 0; q < 4; q++)
            w3[j][q] = Wit[(size_t)(c0 + j) * EW_LD + 256 + q];
    }

    float4 m = make_float4(-1e30f, -1e30f, -1e30f, -1e30f);
    const int s = off[n], e_end = off[n + 1];
    for (int p = s; p < e_end; p++) {
        int2 te = sorted[p];
        float4 bv = *(const float4*)(Bt + (size_t)te.x * H_DIM + c0);
        float4 e4 = *(const float4*)(ef + (size_t)te.y * ETN_DIM);
        float cx = bv.x + bb[0] + e4.x*w3[0][0] + e4.y*w3[0][1] + e4.z*w3[0][2] + e4.w*w3[0][3];
        float cy = bv.y + bb[1] + e4.x*w3[1][0] + e4.y*w3[1][1] + e4.z*w3[1][2] + e4.w*w3[1][3];
        float cz = bv.z + bb[2] + e4.x*w3[2][0] + e4.y*w3[2][1] + e4.z*w3[2][2] + e4.w*w3[2][3];
        float cw = bv.w + bb[3] + e4.x*w3[3][0] + e4.y*w3[3][1] + e4.z*w3[3][2] + e4.w*w3[3][3];
        m.x = fmaxf(m.x, cx); m.y = fmaxf(m.y, cy);
        m.z = fmaxf(m.z, cz); m.w = fmaxf(m.w, cw);
    }

    float4 a = *(const float4*)(A + (size_t)n * H_DIM + c0);
    float4 o;
    if (e_end > s) {
        o.x = fmaxf(0.f, a.x + m.x);
        o.y = fmaxf(0.f, a.y + m.y);
        o.z = fmaxf(0.f, a.z + m.z);
        o.w = fmaxf(0.f, a.w + m.w);
    } else {
        o = make_float4(0.f, 0.f, 0.f, 0.f);
    }
    *(float4*)(cfo + (size_t)n * H_DIM + c0) = o;

    atomicMax(&smax[c0 + 0], encf(o.x));
    atomicMax(&smax[c0 + 1], encf(o.y));
    atomicMax(&smax[c0 + 2], encf(o.z));
    atomicMax(&smax[c0 + 3], encf(o.w));
    __syncthreads();
    if (tid < H_DIM) atomicMax(&pmax[tid], smax[tid]);
}

// ---------------------------------------------------------------------------
// Final heads: parent_feat GEMV (384->128) + geo head (GEMV + group-norm)
// One block, 128 threads.
// ---------------------------------------------------------------------------
__global__ __launch_bounds__(128)
void final_k(const unsigned* __restrict__ p0, const unsigned* __restrict__ p1,
             const unsigned* __restrict__ p2,
             const float* __restrict__ second_w, const float* __restrict__ second_b,
             const unsigned* __restrict__ gcg, const unsigned* __restrict__ gskip,
             const float* __restrict__ sgw, const float* __restrict__ sgb,
             const float* __restrict__ gnw, const float* __restrict__ gnb,
             float* __restrict__ out) {
    __shared__ float pf[384];
    __shared__ float pg[H_DIM];
    __shared__ float sg[H_DIM];
    __shared__ float gv[H_DIM];
    const int t = threadIdx.x;

    pf[t]       = decf(p0[t]);
    pf[128 + t] = decf(p1[t]);
    pf[256 + t] = decf(p2[t]);
    pg[t] = leaky(decf(gcg[t]));
    sg[t] = leaky(decf(gskip[t]));
    __syncthreads();

    // parent_feat
    float acc = second_b[t];
    const float* wr = second_w + (size_t)t * 384;
#pragma unroll 8
    for (int k = 0; k < 384; k++) acc = fmaf(pf[k], wr[k], acc);
    out[t] = leaky(acc);

    // geo GEMV
    float g = sgb[t];
    const float* gr = sgw + (size_t)t * H_DIM;
#pragma unroll 8
    for (int k = 0; k < H_DIM; k++) g = fmaf(pg[k], gr[k], g);
    gv[t] = g;
    __syncthreads();

    // group norm: 16 groups of 8
    const float* gp = &gv[(t >> 3) << 3];
    float mu = 0.f;
#pragma unroll
    for (int i = 0; i < 8; i++) mu += gp[i];
    mu *= 0.125f;
    float var = 0.f;
#pragma unroll
    for (int i = 0; i < 8; i++) { float d = gp[i] - mu; var += d * d; }
    var *= 0.125f;
    float xn = (gv[t] - mu) * rsqrtf(var + 1e-5f);
    float y = xn * gnw[t] + gnb[t];
    out[128 + t] = leaky(sg[t] + y);
}

// ---------------------------------------------------------------------------
// Launch
// ---------------------------------------------------------------------------
extern "C" void kernel_launch(void* const* d_in, const int* in_sizes, int n_in,
                              void* d_out, int out_size) {
    const float* child_feats   = (const float*)d_in[0];
    const float* child_geo     = (const float*)d_in[1];
    const float* child_exists  = (const float*)d_in[2];
    const float* edge_onehot   = (const float*)d_in[3];
    const int*   edge_indices  = (const int*)  d_in[4];
    const float* child_op_w    = (const float*)d_in[5];
    const float* child_op_b    = (const float*)d_in[6];
    const float* second_w      = (const float*)d_in[7];
    const float* second_b      = (const float*)d_in[8];
    const float* edge_w        = (const float*)d_in[9];
    const float* edge_b        = (const float*)d_in[10];
    const float* child_geo_w   = (const float*)d_in[11];
    const float* child_geo_b   = (const float*)d_in[12];
    const float* second_geo_w  = (const float*)d_in[13];
    const float* second_geo_b  = (const float*)d_in[14];
    const float* gn_w          = (const float*)d_in[15];
    const float* gn_b          = (const float*)d_in[16];
    const float* skip_w        = (const float*)d_in[17];
    const float* skip_b        = (const float*)d_in[18];
    float* out = (float*)d_out;

    float *cf0, *cf1, *A, *B;
    int *deg, *off, *cursor;
    int2* sorted;
    unsigned *p0, *p1, *p2, *gcg, *gskip;
    cudaGetSymbolAddress((void**)&cf0,    g_cf0);
    cudaGetSymbolAddress((void**)&cf1,    g_cf1);
    cudaGetSymbolAddress((void**)&A,      g_A);
    cudaGetSymbolAddress((void**)&B,      g_B);
    cudaGetSymbolAddress((void**)&deg,    g_deg);
    cudaGetSymbolAddress((void**)&off,    g_off);
    cudaGetSymbolAddress((void**)&cursor, g_cursor);
    cudaGetSymbolAddress((void**)&sorted, g_sorted);
    cudaGetSymbolAddress((void**)&p0,     g_p0);
    cudaGetSymbolAddress((void**)&p1,     g_p1);
    cudaGetSymbolAddress((void**)&p2,     g_p2);
    cudaGetSymbolAddress((void**)&gcg,    g_gcg);
    cudaGetSymbolAddress((void**)&gskip,  g_gskip);

    const int gemm_grid = (NN + BM - 1) / BM;   // 313
    const int seg_grid  = NN / 8;               // 2500 (exact: 8 warps/block)

    init_k<<<(NN + 255) / 256, 256>>>(deg, p0, p1, p2, gcg, gskip);

    // cf = (child_feats @ Wop^T + b) * exists ; p0 = channel max
    gemm_k<true, true, true><<<gemm_grid, 128>>>(
        child_feats, K_CF, child_op_w, K_CF, child_op_b, child_exists,
        cf0, p0, NN, K_CF);

    // CSR by idx_from (reused for both iterations)
    count_k  <<<(NE + 255) / 256, 256>>>(edge_indices, deg);
    scan_k   <<<1, 1024>>>(deg, off, cursor);
    scatter_k<<<(NE + 255) / 256, 256>>>(edge_indices, cursor, sorted);

    // ---- iteration 0 ----
    gemm_k<false, true, false><<<gemm_grid, 128>>>(
        cf0, H_DIM, edge_w, EW_LD, nullptr, nullptr, A, nullptr, NN, H_DIM);
    gemm_k<false, true, false><<<gemm_grid, 128>>>(
        cf0, H_DIM, edge_w + 128, EW_LD, nullptr, nullptr, B, nullptr, NN, H_DIM);
    segmax_k<<<seg_grid, 256>>>(A, B, sorted, off, edge_onehot,
                                edge_w, edge_b, cf1, p1);

    // ---- iteration 1 ----
    gemm_k<false, true, false><<<gemm_grid, 128>>>(
        cf1, H_DIM, edge_w + EW_ITER_STRIDE, EW_LD, nullptr, nullptr, A, nullptr, NN, H_DIM);
    gemm_k<false, true, false><<<gemm_grid, 128>>>(
        cf1, H_DIM, edge_w + EW_ITER_STRIDE + 128, EW_LD, nullptr, nullptr, B, nullptr, NN, H_DIM);
    segmax_k<<<seg_grid, 256>>>(A, B, sorted, off, edge_onehot,
                                edge_w + EW_ITER_STRIDE, edge_b + 128, cf0, p2);

    // ---- geo path: channel maxima only, no store ----
    gemm_k<true, false, true><<<gemm_grid, 128>>>(
        child_geo, FG_DIM, skip_w, FG_DIM, skip_b, child_exists,
        nullptr, gskip, NN, FG_DIM);
    gemm_k<true, false, true><<<gemm_grid, 128>>>(
        child_geo, FG_DIM, child_geo_w, FG_DIM, child_geo_b, child_exists,
        nullptr, gcg, NN, FG_DIM);

    // ---- heads ----
    final_k<<<1, 128>>>(p0, p1, p2, second_w, second_b, gcg, gskip,
                        second_geo_w, second_geo_b, gn_w, gn_b, out);
}

// round 11
// speedup vs baseline: 1.0097x; 1.0097x over previous
#include <cuda_runtime.h>

// ---------------------------------------------------------------------------
// Problem constants
// ---------------------------------------------------------------------------
#define NN 20000          // N_NODES
#define NE 320000         // N_EDGES
#define H_DIM 128
#define K_CF 162          // NUM_SEM + MAXPP + FS
#define FG_DIM 128
#define ETN_DIM 4
#define EW_LD 260         // 2*H + ETN
#define EW_ITER_STRIDE (128*260)

#define ENC_NEG_INF 0x007FFFFFu   // encf(-inf)

static __device__ __forceinline__ unsigned encf(float f) {
    unsigned u = __float_as_uint(f);
    return (u & 0x80000000u) ? ~u : (u | 0x80000000u);
}
static __device__ __forceinline__ float decf(unsigned e) {
    unsigned u = (e & 0x80000000u) ? (e & 0x7FFFFFFFu) : ~e;
    return __uint_as_float(u);
}
static __device__ __forceinline__ float leaky(float x) {
    return fmaxf(x, 0.01f * x);
}

// ---------------------------------------------------------------------------
// Scratch (static __device__ arrays: no allocations allowed)
// ---------------------------------------------------------------------------
__device__ float   g_cf0[NN * H_DIM];
__device__ float   g_cf1[NN * H_DIM];
__device__ float   g_A  [NN * H_DIM];
__device__ float   g_B  [NN * H_DIM];
__device__ int     g_deg[NN];
__device__ int     g_off[NN + 1];
__device__ int     g_cursor[NN];
__device__ int2    g_sorted[NE];
__device__ unsigned g_p0[H_DIM], g_p1[H_DIM], g_p2[H_DIM];
__device__ unsigned g_gcg[H_DIM], g_gskip[H_DIM];

// ---------------------------------------------------------------------------
// Init: zero degrees, set channel-max accumulators to enc(-inf)
// ---------------------------------------------------------------------------
__global__ void init_k(int* deg, unsigned* p0, unsigned* p1, unsigned* p2,
                       unsigned* gcg, unsigned* gskip) {
    int i = blockIdx.x * blockDim.x + threadIdx.x;
    if (i < NN) deg[i] = 0;
    if (i < H_DIM) {
        p0[i] = ENC_NEG_INF; p1[i] = ENC_NEG_INF; p2[i] = ENC_NEG_INF;
        gcg[i] = ENC_NEG_INF; gskip[i] = ENC_NEG_INF;
    }
}

// ---------------------------------------------------------------------------
// Generic GEMM: C[m][n] = (sum_k X[m][k]*W[n][k] + bias[n]) * (EXISTS? ex[m]:1)
//   X: M x K (row stride ldx), W: 128 x K (row stride ldw), C: M x 128.
//   Optional store, optional per-channel max (encoded uint atomics).
// Tile: BM=64, BN=128, BK=16, 128 threads, 8x8 register tile per thread.
// ---------------------------------------------------------------------------
#define BM 64
#define BN 128
#define BKK 16

template<bool EXISTS, bool STORE, bool CMAX>
__global__ __launch_bounds__(128)
void gemm_k(const float* __restrict__ X, int ldx,
            const float* __restrict__ W, int ldw,
            const float* __restrict__ bias,
            const float* __restrict__ ex,
            float* __restrict__ C,
            unsigned* __restrict__ cmax,
            int M, int K) {
    __shared__ float As[BKK][BM + 4];
    __shared__ float Bs[BKK][BN + 4];
    __shared__ unsigned smax[BN];

    const int tid = threadIdx.x;
    const int tr = tid >> 4;   // 0..7
    const int tc = tid & 15;   // 0..15
    const int m0 = blockIdx.x * BM;

    if (CMAX) smax[tid] = ENC_NEG_INF;   // blockDim == 128 == BN

    float acc[8][8];
#pragma unroll
    for (int i = 0; i < 8; i++)
#pragma unroll
        for (int j = 0; j < 8; j++) acc[i][j] = 0.f;

    for (int k0 = 0; k0 < K; k0 += BKK) {
        // Load A tile (64x16), transposed into As[k][m]
#pragma unroll
        for (int i = 0; i < 8; i++) {
            int idx = tid + 128 * i;
            int m = idx >> 4, k = idx & 15;
            int gm = m0 + m, gk = k0 + k;
            As[k][m] = (gm < M && gk < K) ? X[(size_t)gm * ldx + gk] : 0.f;
        }
        // Load B tile (128 rows of W, 16 k) into Bs[k][n]
#pragma unroll
        for (int i = 0; i < 16; i++) {
            int idx = tid + 128 * i;
            int n = idx >> 4, k = idx & 15;
            int gk = k0 + k;
            Bs[k][n] = (gk < K) ? W[(size_t)n * ldw + gk] : 0.f;
        }
        __syncthreads();

#pragma unroll
        for (int kk = 0; kk < BKK; kk++) {
            float4 a0 = *(const float4*)&As[kk][tr * 8];
            float4 a1 = *(const float4*)&As[kk][tr * 8 + 4];
            float4 b0 = *(const float4*)&Bs[kk][tc * 8];
            float4 b1 = *(const float4*)&Bs[kk][tc * 8 + 4];
            float a[8] = {a0.x, a0.y, a0.z, a0.w, a1.x, a1.y, a1.z, a1.w};
            float b[8] = {b0.x, b0.y, b0.z, b0.w, b1.x, b1.y, b1.z, b1.w};
#pragma unroll
            for (int i = 0; i < 8; i++)
#pragma unroll
                for (int j = 0; j < 8; j++)
                    acc[i][j] = fmaf(a[i], b[j], acc[i][j]);
        }
        __syncthreads();
    }

    // Epilogue
    float bv[8];
#pragma unroll
    for (int j = 0; j < 8; j++) bv[j] = bias ? bias[tc * 8 + j] : 0.f;

    unsigned cm[8];
#pragma unroll
    for (int j = 0; j < 8; j++) cm[j] = ENC_NEG_INF;

#pragma unroll
    for (int i = 0; i < 8; i++) {
        int gm = m0 + tr * 8 + i;
        if (gm < M) {
            float e = EXISTS ? ex[gm] : 1.f;
#pragma unroll
            for (int j = 0; j < 8; j++) {
                float v = (acc[i][j] + bv[j]) * e;
                if (STORE) C[(size_t)gm * BN + tc * 8 + j] = v;
                if (CMAX)  cm[j] = max(cm[j], encf(v));
            }
        }
    }

    if (CMAX) {
        // syncthreads in main loop guarantees smax init is visible
#pragma unroll
        for (int j = 0; j < 8; j++) atomicMax(&smax[tc * 8 + j], cm[j]);
        __syncthreads();
        atomicMax(&cmax[tid], smax[tid]);
    }
}

// ---------------------------------------------------------------------------
// CSR build: count / scan / scatter
// ---------------------------------------------------------------------------
__global__ void count_k(const int* __restrict__ ei, int* __restrict__ deg) {
    int e = blockIdx.x * blockDim.x + threadIdx.x;
    if (e < NE) atomicAdd(&deg[ei[2 * e]], 1);
}

__global__ __launch_bounds__(1024)
void scan_k(const int* __restrict__ deg, int* __restrict__ off,
            int* __restrict__ cursor) {
    __shared__ int tsum[1024];
    const int t = threadIdx.x;
    const int IT = 20;                       // 1024*20 >= 20000
    const int base = t * IT;
    int local[IT];
    int s = 0;
#pragma unroll
    for (int i = 0; i < IT; i++) {
        int idx = base + i;
        int v = (idx < NN) ? deg[idx] : 0;
        local[i] = s;
        s += v;
    }
    tsum[t] = s;
    __syncthreads();
    // Hillis-Steele inclusive scan
    for (int d = 1; d < 1024; d <<= 1) {
        int v = (t >= d) ? tsum[t - d] : 0;
        __syncthreads();
        tsum[t] += v;
        __syncthreads();
    }
    int excl = (t == 0) ? 0 : tsum[t - 1];
#pragma unroll
    for (int i = 0; i < IT; i++) {
        int idx = base + i;
        if (idx < NN) {
            int o = excl + local[i];
            off[idx] = o;
            cursor[idx] = o;
        }
    }
    if (t == 0) off[NN] = tsum[1023];
}

__global__ void scatter_k(const int* __restrict__ ei, int* __restrict__ cursor,
                          int2* __restrict__ sorted) {
    int e = blockIdx.x * blockDim.x + threadIdx.x;
    if (e < NE) {
        int f = ei[2 * e];
        int to = ei[2 * e + 1];
        int p = atomicAdd(&cursor[f], 1);
        sorted[p] = make_int2(to, e);
    }
}

// ---------------------------------------------------------------------------
// Segmented max per node (warp per node, 4 channels per lane):
//   M[h]      = max_{e: from=n} (B[to_e][h] + edge_b[h] + ef[e] . W3[h])
//   cf_new[n] = relu(A[n] + M)   (0 if degree 0)
// Also accumulates per-channel max over nodes (p_{i+1}).
// Grid must cover exactly NN warps (NN % warps_per_block == 0).
// ---------------------------------------------------------------------------
__global__ __launch_bounds__(256)
void segmax_k(const float* __restrict__ A, const float* __restrict__ Bt,
              const int2* __restrict__ sorted, const int* __restrict__ off,
              const float* __restrict__ ef,
              const float* __restrict__ Wit,   // edge_w + iter*128*260
              const float* __restrict__ bit,   // edge_b + iter*128
              float* __restrict__ cfo, unsigned* __restrict__ pmax) {
    __shared__ unsigned smax[H_DIM];
    const int tid = threadIdx.x;
    if (tid < H_DIM) smax[tid] = ENC_NEG_INF;
    __syncthreads();

    const int warp = tid >> 5, lane = tid & 31;
    const int n = blockIdx.x * (blockDim.x >> 5) + warp;   // always < NN (exact grid)
    const int c0 = lane * 4;

    float w3[4][4], bb[4];
#pragma unroll
    for (int j = 0; j < 4; j++) {
        bb[j] = bit[c0 + j];
#pragma unroll
        for (int q = 0; q < 4; q++)
            w3[j][q] = Wit[(size_t)(c0 + j) * EW_LD + 256 + q];
    }

    float4 m = make_float4(-1e30f, -1e30f, -1e30f, -1e30f);
    const int s = off[n], e_end = off[n + 1];
    for (int p = s; p < e_end; p++) {
        int2 te = sorted[p];
        float4 bv = *(const float4*)(Bt + (size_t)te.x * H_DIM + c0);
        float4 e4 = *(const float4*)(ef + (size_t)te.y * ETN_DIM);
        float cx = bv.x + bb[0] + e4.x*w3[0][0] + e4.y*w3[0][1] + e4.z*w3[0][2] + e4.w*w3[0][3];
        float cy = bv.y + bb[1] + e4.x*w3[1][0] + e4.y*w3[1][1] + e4.z*w3[1][2] + e4.w*w3[1][3];
        float cz = bv.z + bb[2] + e4.x*w3[2][0] + e4.y*w3[2][1] + e4.z*w3[2][2] + e4.w*w3[2][3];
        float cw = bv.w + bb[3] + e4.x*w3[3][0] + e4.y*w3[3][1] + e4.z*w3[3][2] + e4.w*w3[3][3];
        m.x = fmaxf(m.x, cx); m.y = fmaxf(m.y, cy);
        m.z = fmaxf(m.z, cz); m.w = fmaxf(m.w, cw);
    }

    float4 a = *(const float4*)(A + (size_t)n * H_DIM + c0);
    float4 o;
    if (e_end > s) {
        o.x = fmaxf(0.f, a.x + m.x);
        o.y = fmaxf(0.f, a.y + m.y);
        o.z = fmaxf(0.f, a.z + m.z);
        o.w = fmaxf(0.f, a.w + m.w);
    } else {
        o = make_float4(0.f, 0.f, 0.f, 0.f);
    }
    *(float4*)(cfo + (size_t)n * H_DIM + c0) = o;

    atomicMax(&smax[c0 + 0], encf(o.x));
    atomicMax(&smax[c0 + 1], encf(o.y));
    atomicMax(&smax[c0 + 2], encf(o.z));
    atomicMax(&smax[c0 + 3], encf(o.w));
    __syncthreads();
    if (tid < H_DIM) atomicMax(&pmax[tid], smax[tid]);
}

// ---------------------------------------------------------------------------
// Final heads: parent_feat GEMV (384->128) + geo head (GEMV + group-norm)
// One block, 128 threads.
// ---------------------------------------------------------------------------
__global__ __launch_bounds__(128)
void final_k(const unsigned* __restrict__ p0, const unsigned* __restrict__ p1,
             const unsigned* __restrict__ p2,
             const float* __restrict__ second_w, const float* __restrict__ second_b,
             const unsigned* __restrict__ gcg, const unsigned* __restrict__ gskip,
             const float* __restrict__ sgw, const float* __restrict__ sgb,
             const float* __restrict__ gnw, const float* __restrict__ gnb,
             float* __restrict__ out) {
    __shared__ float pf[384];
    __shared__ float pg[H_DIM];
    __shared__ float sg[H_DIM];
    __shared__ float gv[H_DIM];
    const int t = threadIdx.x;

    pf[t]       = decf(p0[t]);
    pf[128 + t] = decf(p1[t]);
    pf[256 + t] = decf(p2[t]);
    pg[t] = leaky(decf(gcg[t]));
    sg[t] = leaky(decf(gskip[t]));
    __syncthreads();

    // parent_feat
    float acc = second_b[t];
    const float* wr = second_w + (size_t)t * 384;
#pragma unroll 8
    for (int k = 0; k < 384; k++) acc = fmaf(pf[k], wr[k], acc);
    out[t] = leaky(acc);

    // geo GEMV
    float g = sgb[t];
    const float* gr = sgw + (size_t)t * H_DIM;
#pragma unroll 8
    for (int k = 0; k < H_DIM; k++) g = fmaf(pg[k], gr[k], g);
    gv[t] = g;
    __syncthreads();

    // group norm: 16 groups of 8
    const float* gp = &gv[(t >> 3) << 3];
    float mu = 0.f;
#pragma unroll
    for (int i = 0; i < 8; i++) mu += gp[i];
    mu *= 0.125f;
    float var = 0.f;
#pragma unroll
    for (int i = 0; i < 8; i++) { float d = gp[i] - mu; var += d * d; }
    var *= 0.125f;
    float xn = (gv[t] - mu) * rsqrtf(var + 1e-5f);
    float y = xn * gnw[t] + gnb[t];
    out[128 + t] = leaky(sg[t] + y);
}

// ---------------------------------------------------------------------------
// Launch
// ---------------------------------------------------------------------------
extern "C" void kernel_launch(void* const* d_in, const int* in_sizes, int n_in,
                              void* d_out, int out_size) {
    const float* child_feats   = (const float*)d_in[0];
    const float* child_geo     = (const float*)d_in[1];
    const float* child_exists  = (const float*)d_in[2];
    const float* edge_onehot   = (const float*)d_in[3];
    const int*   edge_indices  = (const int*)  d_in[4];
    const float* child_op_w    = (const float*)d_in[5];
    const float* child_op_b    = (const float*)d_in[6];
    const float* second_w      = (const float*)d_in[7];
    const float* second_b      = (const float*)d_in[8];
    const float* edge_w        = (const float*)d_in[9];
    const float* edge_b        = (const float*)d_in[10];
    const float* child_geo_w   = (const float*)d_in[11];
    const float* child_geo_b   = (const float*)d_in[12];
    const float* second_geo_w  = (const float*)d_in[13];
    const float* second_geo_b  = (const float*)d_in[14];
    const float* gn_w          = (const float*)d_in[15];
    const float* gn_b          = (const float*)d_in[16];
    const float* skip_w        = (const float*)d_in[17];
    const float* skip_b        = (const float*)d_in[18];
    float* out = (float*)d_out;

    float *cf0, *cf1, *A, *B;
    int *deg, *off, *cursor;
    int2* sorted;
    unsigned *p0, *p1, *p2, *gcg, *gskip;
    cudaGetSymbolAddress((void**)&cf0,    g_cf0);
    cudaGetSymbolAddress((void**)&cf1,    g_cf1);
    cudaGetSymbolAddress((void**)&A,      g_A);
    cudaGetSymbolAddress((void**)&B,      g_B);
    cudaGetSymbolAddress((void**)&deg,    g_deg);
    cudaGetSymbolAddress((void**)&off,    g_off);
    cudaGetSymbolAddress((void**)&cursor, g_cursor);
    cudaGetSymbolAddress((void**)&sorted, g_sorted);
    cudaGetSymbolAddress((void**)&p0,     g_p0);
    cudaGetSymbolAddress((void**)&p1,     g_p1);
    cudaGetSymbolAddress((void**)&p2,     g_p2);
    cudaGetSymbolAddress((void**)&gcg,    g_gcg);
    cudaGetSymbolAddress((void**)&gskip,  g_gskip);

    const int gemm_grid = (NN + BM - 1) / BM;   // 313
    const int seg_grid  = NN / 8;               // 2500 (exact: 8 warps/block)

    init_k<<<(NN + 255) / 256, 256>>>(deg, p0, p1, p2, gcg, gskip);

    // cf = (child_feats @ Wop^T + b) * exists ; p0 = channel max
    gemm_k<true, true, true><<<gemm_grid, 128>>>(
        child_feats, K_CF, child_op_w, K_CF, child_op_b, child_exists,
        cf0, p0, NN, K_CF);

    // CSR by idx_from (reused for both iterations)
    count_k  <<<(NE + 255) / 256, 256>>>(edge_indices, deg);
    scan_k   <<<1, 1024>>>(deg, off, cursor);
    scatter_k<<<(NE + 255) / 256, 256>>>(edge_indices, cursor, sorted);

    // ---- iteration 0 ----
    gemm_k<false, true, false><<<gemm_grid, 128>>>(
        cf0, H_DIM, edge_w, EW_LD, nullptr, nullptr, A, nullptr, NN, H_DIM);
    gemm_k<false, true, false><<<gemm_grid, 128>>>(
        cf0, H_DIM, edge_w + 128, EW_LD, nullptr, nullptr, B, nullptr, NN, H_DIM);
    segmax_k<<<seg_grid, 256>>>(A, B, sorted, off, edge_onehot,
                                edge_w, edge_b, cf1, p1);

    // ---- iteration 1 ----
    gemm_k<false, true, false><<<gemm_grid, 128>>>(
        cf1, H_DIM, edge_w + EW_ITER_STRIDE, EW_LD, nullptr, nullptr, A, nullptr, NN, H_DIM);
    gemm_k<false, true, false><<<gemm_grid, 128>>>(
        cf1, H_DIM, edge_w + EW_ITER_STRIDE + 128, EW_LD, nullptr, nullptr, B, nullptr, NN, H_DIM);
    segmax_k<<<seg_grid, 256>>>(A, B, sorted, off, edge_onehot,
                                edge_w + EW_ITER_STRIDE, edge_b + 128, cf0, p2);

    // ---- geo path: channel maxima only, no store ----
    gemm_k<true, false, true><<<gemm_grid, 128>>>(
        child_geo, FG_DIM, skip_w, FG_DIM, skip_b, child_exists,
        nullptr, gskip, NN, FG_DIM);
    gemm_k<true, false, true><<<gemm_grid, 128>>>(
        child_geo, FG_DIM, child_geo_w, FG_DIM, child_geo_b, child_exists,
        nullptr, gcg, NN, FG_DIM);

    // ---- heads ----
    final_k<<<1, 128>>>(p0, p1, p2, second_w, second_b, gcg, gskip,
                        second_geo_w, second_geo_b, gn_w, gn_b, out);
}

// round 12
// speedup vs baseline: 1.0717x; 1.0614x over previous
#include <cuda_runtime.h>

// ---------------------------------------------------------------------------
// Problem constants
// ---------------------------------------------------------------------------
#define NN 20000          // N_NODES
#define NE 320000         // N_EDGES
#define H_DIM 128
#define K_CF 162          // NUM_SEM + MAXPP + FS
#define FG_DIM 128
#define EW_LD 260         // 2*H + ETN
#define EW_ITER_STRIDE (128*260)
#define CAP 64            // bucket capacity per node (P(deg>=64) ~ 4e-18)

#define ENC_NEG_INF 0x007FFFFFu   // encf(-inf)

static __device__ __forceinline__ unsigned encf(float f) {
    unsigned u = __float_as_uint(f);
    return (u & 0x80000000u) ? ~u : (u | 0x80000000u);
}
static __device__ __forceinline__ float decf(unsigned e) {
    unsigned u = (e & 0x80000000u) ? (e & 0x7FFFFFFFu) : ~e;
    return __uint_as_float(u);
}
static __device__ __forceinline__ float leaky(float x) {
    return fmaxf(x, 0.01f * x);
}

// ---------------------------------------------------------------------------
// Scratch (static __device__ arrays: no allocations allowed)
// ---------------------------------------------------------------------------
__device__ float   g_cf0[NN * H_DIM];
__device__ float   g_cf1[NN * H_DIM];
__device__ float   g_AB [NN * 256];          // interleaved: A in cols [0,128), B in [128,256)
__device__ int     g_deg[NN];
__device__ int2    g_slots[(size_t)NN * CAP];
__device__ unsigned g_p0[H_DIM], g_p1[H_DIM], g_p2[H_DIM];
__device__ unsigned g_gcg[H_DIM], g_gskip[H_DIM];

// ---------------------------------------------------------------------------
// Init: zero degrees, set channel-max accumulators to enc(-inf)
// ---------------------------------------------------------------------------
__global__ void init_k(int* deg, unsigned* p0, unsigned* p1, unsigned* p2,
                       unsigned* gcg, unsigned* gskip) {
    int i = blockIdx.x * blockDim.x + threadIdx.x;
    if (i < NN) deg[i] = 0;
    if (i < H_DIM) {
        p0[i] = ENC_NEG_INF; p1[i] = ENC_NEG_INF; p2[i] = ENC_NEG_INF;
        gcg[i] = ENC_NEG_INF; gskip[i] = ENC_NEG_INF;
    }
}

// ---------------------------------------------------------------------------
// Bucket scatter: one pass, no count, no scan.
//   slots[f*CAP + pos] = (to, e)
// ---------------------------------------------------------------------------
__global__ void scatter_k(const int* __restrict__ ei, int* __restrict__ deg,
                          int2* __restrict__ slots) {
    int e = blockIdx.x * blockDim.x + threadIdx.x;
    if (e < NE) {
        int f  = ei[2 * e];
        int to = ei[2 * e + 1];
        int p = atomicAdd(&deg[f], 1);
        if (p < CAP) slots[(size_t)f * CAP + p] = make_int2(to, e);
    }
}

// ---------------------------------------------------------------------------
// Fused GEMM: C[m][n] = (sum_k X[m][k]*Wrow_n[k] + bias_n) * (EXISTS? ex[m]:1)
//   Wrow_n = W1 + n*ldw          for n < 128
//          = W2 + (n-128)*ldw    for n >= 128   (BN_T == 256)
//   bias_n from bias1 (n<128) / bias2 (n>=128), nullptr -> 0.
//   Optional store (row stride BN_T), optional per-channel max into
//   cmax1 (cols <128) / cmax2 (cols >=128).
// Tile: BM=64, BN_T in {128,256}, BK=16, 256 threads, 8 x (BN_T/32) per thread.
// Warp w owns rows w*8..w*8+7 (A-row smem reads are warp-uniform broadcasts).
// ---------------------------------------------------------------------------
#define BM 64
#define BKT 16

template<int BN_T, bool EXISTS, bool STORE, bool CMAX>
__global__ __launch_bounds__(256)
void gemm2_k(const float* __restrict__ X, int ldx,
             const float* __restrict__ W1, const float* __restrict__ W2, int ldw,
             const float* __restrict__ bias1, const float* __restrict__ bias2,
             const float* __restrict__ ex,
             float* __restrict__ C,
             unsigned* __restrict__ cmax1, unsigned* __restrict__ cmax2,
             int M, int K) {
    constexpr int CN = BN_T / 32;
    __shared__ float As[BKT][BM + 4];
    __shared__ float Bs[BKT][BN_T + 4];
    __shared__ unsigned smax[BN_T];

    const int tid  = threadIdx.x;
    const int warp = tid >> 5;
    const int lane = tid & 31;
    const int m0   = blockIdx.x * BM;
    const int colBase = lane * CN;

    if (CMAX) {
        for (int i = tid; i < BN_T; i += 256) smax[i] = ENC_NEG_INF;
    }

    float acc[8][CN];
#pragma unroll
    for (int i = 0; i < 8; i++)
#pragma unroll
        for (int j = 0; j < CN; j++) acc[i][j] = 0.f;

    for (int k0 = 0; k0 < K; k0 += BKT) {
        // A tile: 64 x 16 = 1024 elems, 4 per thread
#pragma unroll
        for (int i = 0; i < 4; i++) {
            int lin = tid + 256 * i;
            int mm = lin >> 4, kk = lin & 15;
            int gm = m0 + mm, gk = k0 + kk;
            As[kk][mm] = (gm < M && gk < K) ? X[(size_t)gm * ldx + gk] : 0.f;
        }
        // B tile: BN_T x 16 elems
#pragma unroll
        for (int i = 0; i < BN_T / 16; i++) {
            int lin = tid + 256 * i;
            int nn = lin >> 4, kk = lin & 15;
            int gk = k0 + kk;
            const float* wrow = (BN_T == 128 || nn < 128)
                                    ? (W1 + (size_t)nn * ldw)
                                    : (W2 + (size_t)(nn - 128) * ldw);
            Bs[kk][nn] = (gk < K) ? wrow[gk] : 0.f;
        }
        __syncthreads();

#pragma unroll
        for (int kk = 0; kk < BKT; kk++) {
            float a[8];
            *(float4*)&a[0] = *(const float4*)&As[kk][warp * 8];
            *(float4*)&a[4] = *(const float4*)&As[kk][warp * 8 + 4];
            float b[CN];
#pragma unroll
            for (int q = 0; q < CN; q += 4)
                *(float4*)&b[q] = *(const float4*)&Bs[kk][colBase + q];
#pragma unroll
            for (int i = 0; i < 8; i++)
#pragma unroll
                for (int j = 0; j < CN; j++)
                    acc[i][j] = fmaf(a[i], b[j], acc[i][j]);
        }
        __syncthreads();
    }

    // Epilogue
    float bv[CN];
#pragma unroll
    for (int j = 0; j < CN; j++) {
        int col = colBase + j;
        if (BN_T == 128 || col < 128)
            bv[j] = bias1 ? bias1[col] : 0.f;
        else
            bv[j] = bias2 ? bias2[col - 128] : 0.f;
    }

    unsigned cm[CN];
#pragma unroll
    for (int j = 0; j < CN; j++) cm[j] = ENC_NEG_INF;

#pragma unroll
    for (int i = 0; i < 8; i++) {
        int gm = m0 + warp * 8 + i;
        if (gm < M) {
            float e = EXISTS ? ex[gm] : 1.f;
            float v[CN];
#pragma unroll
            for (int j = 0; j < CN; j++) {
                v[j] = (acc[i][j] + bv[j]) * e;
                if (CMAX) cm[j] = max(cm[j], encf(v[j]));
            }
            if (STORE) {
#pragma unroll
                for (int q = 0; q < CN; q += 4)
                    *(float4*)&C[(size_t)gm * BN_T + colBase + q] =
                        make_float4(v[q], v[q + 1], v[q + 2], v[q + 3]);
            }
        }
    }

    if (CMAX) {
#pragma unroll
        for (int j = 0; j < CN; j++) atomicMax(&smax[colBase + j], cm[j]);
        __syncthreads();
        for (int i = tid; i < BN_T; i += 256) {
            unsigned* dst = (BN_T == 128 || i < 128) ? &cmax1[i] : &cmax2[i - 128];
            atomicMax(dst, smax[i]);
        }
    }
}

// ---------------------------------------------------------------------------
// Segmented max per node (warp per node, 4 channels per lane):
//   M[h]      = max_{e: from=n} (B[to_e][h] + edge_b[h] + ef[e] . W3[h])
//   cf_new[n] = relu(A[n] + M)   (0 if degree 0)
// A at AB[n*256 + c], B rows at AB[to*256 + 128 + c].
// Also accumulates per-channel max over nodes (pmax).
// ---------------------------------------------------------------------------
__global__ __launch_bounds__(256)
void segmax_k(const float* __restrict__ AB,
              const int2* __restrict__ slots, const int* __restrict__ deg,
              const float* __restrict__ ef,
              const float* __restrict__ Wit,   // edge_w + iter*128*260
              const float* __restrict__ bit,   // edge_b + iter*128
              float* __restrict__ cfo, unsigned* __restrict__ pmax) {
    __shared__ unsigned smax[H_DIM];
    const int tid = threadIdx.x;
    if (tid < H_DIM) smax[tid] = ENC_NEG_INF;
    __syncthreads();

    const int warp = tid >> 5, lane = tid & 31;
    const int n = blockIdx.x * (blockDim.x >> 5) + warp;   // exact grid: always < NN
    const int c0 = lane * 4;

    float w3[4][4], bb[4];
#pragma unroll
    for (int j = 0; j < 4; j++) {
        bb[j] = bit[c0 + j];
#pragma unroll
        for (int q = 0; q < 4; q++)
            w3[j][q] = Wit[(size_t)(c0 + j) * EW_LD + 256 + q];
    }

    float4 m = make_float4(-1e30f, -1e30f, -1e30f, -1e30f);
    const int d = min(deg[n], CAP);
    const int2* sl = slots + (size_t)n * CAP;
    for (int p = 0; p < d; p++) {
        int2 te = sl[p];
        float4 bv = *(const float4*)(AB + (size_t)te.x * 256 + 128 + c0);
        float4 e4 = *(const float4*)(ef + (size_t)te.y * 4);
        float cx = bv.x + bb[0] + e4.x*w3[0][0] + e4.y*w3[0][1] + e4.z*w3[0][2] + e4.w*w3[0][3];
        float cy = bv.y + bb[1] + e4.x*w3[1][0] + e4.y*w3[1][1] + e4.z*w3[1][2] + e4.w*w3[1][3];
        float cz = bv.z + bb[2] + e4.x*w3[2][0] + e4.y*w3[2][1] + e4.z*w3[2][2] + e4.w*w3[2][3];
        float cw = bv.w + bb[3] + e4.x*w3[3][0] + e4.y*w3[3][1] + e4.z*w3[3][2] + e4.w*w3[3][3];
        m.x = fmaxf(m.x, cx); m.y = fmaxf(m.y, cy);
        m.z = fmaxf(m.z, cz); m.w = fmaxf(m.w, cw);
    }

    float4 a = *(const float4*)(AB + (size_t)n * 256 + c0);
    float4 o;
    if (d > 0) {
        o.x = fmaxf(0.f, a.x + m.x);
        o.y = fmaxf(0.f, a.y + m.y);
        o.z = fmaxf(0.f, a.z + m.z);
        o.w = fmaxf(0.f, a.w + m.w);
    } else {
        o = make_float4(0.f, 0.f, 0.f, 0.f);
    }
    *(float4*)(cfo + (size_t)n * H_DIM + c0) = o;

    atomicMax(&smax[c0 + 0], encf(o.x));
    atomicMax(&smax[c0 + 1], encf(o.y));
    atomicMax(&smax[c0 + 2], encf(o.z));
    atomicMax(&smax[c0 + 3], encf(o.w));
    __syncthreads();
    if (tid < H_DIM) atomicMax(&pmax[tid], smax[tid]);
}

// ---------------------------------------------------------------------------
// Final heads: parent_feat GEMV (384->128) + geo head (GEMV + group-norm)
// One block, 128 threads.
// ---------------------------------------------------------------------------
__global__ __launch_bounds__(128)
void final_k(const unsigned* __restrict__ p0, const unsigned* __restrict__ p1,
             const unsigned* __restrict__ p2,
             const float* __restrict__ second_w, const float* __restrict__ second_b,
             const unsigned* __restrict__ gcg, const unsigned* __restrict__ gskip,
             const float* __restrict__ sgw, const float* __restrict__ sgb,
             const float* __restrict__ gnw, const float* __restrict__ gnb,
             float* __restrict__ out) {
    __shared__ float pf[384];
    __shared__ float pg[H_DIM];
    __shared__ float sg[H_DIM];
    __shared__ float gv[H_DIM];
    const int t = threadIdx.x;

    pf[t]       = decf(p0[t]);
    pf[128 + t] = decf(p1[t]);
    pf[256 + t] = decf(p2[t]);
    pg[t] = leaky(decf(gcg[t]));
    sg[t] = leaky(decf(gskip[t]));
    __syncthreads();

    // parent_feat
    float acc = second_b[t];
    const float* wr = second_w + (size_t)t * 384;
#pragma unroll 8
    for (int k = 0; k < 384; k++) acc = fmaf(pf[k], wr[k], acc);
    out[t] = leaky(acc);

    // geo GEMV
    float g = sgb[t];
    const float* gr = sgw + (size_t)t * H_DIM;
#pragma unroll 8
    for (int k = 0; k < H_DIM; k++) g = fmaf(pg[k], gr[k], g);
    gv[t] = g;
    __syncthreads();

    // group norm: 16 groups of 8
    const float* gp = &gv[(t >> 3) << 3];
    float mu = 0.f;
#pragma unroll
    for (int i = 0; i < 8; i++) mu += gp[i];
    mu *= 0.125f;
    float var = 0.f;
#pragma unroll
    for (int i = 0; i < 8; i++) { float dd = gp[i] - mu; var += dd * dd; }
    var *= 0.125f;
    float xn = (gv[t] - mu) * rsqrtf(var + 1e-5f);
    float y = xn * gnw[t] + gnb[t];
    out[128 + t] = leaky(sg[t] + y);
}

// ---------------------------------------------------------------------------
// Launch
// ---------------------------------------------------------------------------
extern "C" void kernel_launch(void* const* d_in, const int* in_sizes, int n_in,
                              void* d_out, int out_size) {
    const float* child_feats   = (const float*)d_in[0];
    const float* child_geo     = (const float*)d_in[1];
    const float* child_exists  = (const float*)d_in[2];
    const float* edge_onehot   = (const float*)d_in[3];
    const int*   edge_indices  = (const int*)  d_in[4];
    const float* child_op_w    = (const float*)d_in[5];
    const float* child_op_b    = (const float*)d_in[6];
    const float* second_w      = (const float*)d_in[7];
    const float* second_b      = (const float*)d_in[8];
    const float* edge_w        = (const float*)d_in[9];
    const float* edge_b        = (const float*)d_in[10];
    const float* child_geo_w   = (const float*)d_in[11];
    const float* child_geo_b   = (const float*)d_in[12];
    const float* second_geo_w  = (const float*)d_in[13];
    const float* second_geo_b  = (const float*)d_in[14];
    const float* gn_w          = (const float*)d_in[15];
    const float* gn_b          = (const float*)d_in[16];
    const float* skip_w        = (const float*)d_in[17];
    const float* skip_b        = (const float*)d_in[18];
    float* out = (float*)d_out;

    float *cf0, *cf1, *AB;
    int *deg;
    int2* slots;
    unsigned *p0, *p1, *p2, *gcg, *gskip;
    cudaGetSymbolAddress((void**)&cf0,   g_cf0);
    cudaGetSymbolAddress((void**)&cf1,   g_cf1);
    cudaGetSymbolAddress((void**)&AB,    g_AB);
    cudaGetSymbolAddress((void**)&deg,   g_deg);
    cudaGetSymbolAddress((void**)&slots, g_slots);
    cudaGetSymbolAddress((void**)&p0,    g_p0);
    cudaGetSymbolAddress((void**)&p1,    g_p1);
    cudaGetSymbolAddress((void**)&p2,    g_p2);
    cudaGetSymbolAddress((void**)&gcg,   g_gcg);
    cudaGetSymbolAddress((void**)&gskip, g_gskip);

    const int gemm_grid = (NN + BM - 1) / BM;   // 313
    const int seg_grid  = NN / 8;               // 2500 (8 warps/block, exact)

    init_k<<<(NN + 255) / 256, 256>>>(deg, p0, p1, p2, gcg, gskip);

    // Grouping by idx_from: single-pass bucket scatter (no count, no scan)
    scatter_k<<<(NE + 255) / 256, 256>>>(edge_indices, deg, slots);

    // cf0 = (child_feats @ Wop^T + b) * exists ; p0 = channel max
    gemm2_k<128, true, true, true><<<gemm_grid, 256>>>(
        child_feats, K_CF, child_op_w, nullptr, K_CF, child_op_b, nullptr,
        child_exists, cf0, p0, nullptr, NN, K_CF);

    // ---- iteration 0: fused A|B projection, then segmented max ----
    gemm2_k<256, false, true, false><<<gemm_grid, 256>>>(
        cf0, H_DIM, edge_w, edge_w + 128, EW_LD, nullptr, nullptr,
        nullptr, AB, nullptr, nullptr, NN, H_DIM);
    segmax_k<<<seg_grid, 256>>>(AB, slots, deg, edge_onehot,
                                edge_w, edge_b, cf1, p1);

    // ---- iteration 1 ----
    gemm2_k<256, false, true, false><<<gemm_grid, 256>>>(
        cf1, H_DIM, edge_w + EW_ITER_STRIDE, edge_w + EW_ITER_STRIDE + 128,
        EW_LD, nullptr, nullptr, nullptr, AB, nullptr, nullptr, NN, H_DIM);
    segmax_k<<<seg_grid, 256>>>(AB, slots, deg, edge_onehot,
                                edge_w + EW_ITER_STRIDE, edge_b + 128, cf0, p2);

    // ---- geo path: fused skip|cg projection, channel maxima only ----
    gemm2_k<256, true, false, true><<<gemm_grid, 256>>>(
        child_geo, FG_DIM, skip_w, child_geo_w, FG_DIM, skip_b, child_geo_b,
        child_exists, nullptr, gskip, gcg, NN, FG_DIM);

    // ---- heads ----
    final_k<<<1, 128>>>(p0, p1, p2, second_w, second_b, gcg, gskip,
                        second_geo_w, second_geo_b, gn_w, gn_b, out);
}

// round 13
// speedup vs baseline: 1.0739x; 1.0020x over previous
#include <cuda_runtime.h>

// ---------------------------------------------------------------------------
// Problem constants
// ---------------------------------------------------------------------------
#define NN 20000          // N_NODES
#define NE 320000         // N_EDGES
#define H_DIM 128
#define K_CF 162          // NUM_SEM + MAXPP + FS
#define FG_DIM 128
#define EW_LD 260         // 2*H + ETN
#define EW_ITER_STRIDE (128*260)
#define CAP 64            // bucket capacity per node (P(deg>=64) ~ 4e-18)

#define ENC_NEG_INF 0x007FFFFFu   // encf(-inf)

static __device__ __forceinline__ unsigned encf(float f) {
    unsigned u = __float_as_uint(f);
    return (u & 0x80000000u) ? ~u : (u | 0x80000000u);
}
static __device__ __forceinline__ float decf(unsigned e) {
    unsigned u = (e & 0x80000000u) ? (e & 0x7FFFFFFFu) : ~e;
    return __uint_as_float(u);
}
static __device__ __forceinline__ float leaky(float x) {
    return fmaxf(x, 0.01f * x);
}

// ---------------------------------------------------------------------------
// Scratch (static __device__ arrays: no allocations allowed)
// ---------------------------------------------------------------------------
__device__ float   g_cf0[NN * H_DIM];
__device__ float   g_cf1[NN * H_DIM];
__device__ float   g_AB [NN * 256];          // interleaved: A in cols [0,128), B in [128,256)
__device__ int     g_deg[NN];
__device__ int2    g_slots[(size_t)NN * CAP];
__device__ unsigned g_p0[H_DIM], g_p1[H_DIM], g_p2[H_DIM];
__device__ unsigned g_gcg[H_DIM], g_gskip[H_DIM];

// ---------------------------------------------------------------------------
// Init: zero degrees, set channel-max accumulators to enc(-inf)
// ---------------------------------------------------------------------------
__global__ void init_k(int* deg, unsigned* p0, unsigned* p1, unsigned* p2,
                       unsigned* gcg, unsigned* gskip) {
    int i = blockIdx.x * blockDim.x + threadIdx.x;
    if (i < NN) deg[i] = 0;
    if (i < H_DIM) {
        p0[i] = ENC_NEG_INF; p1[i] = ENC_NEG_INF; p2[i] = ENC_NEG_INF;
        gcg[i] = ENC_NEG_INF; gskip[i] = ENC_NEG_INF;
    }
}

// ---------------------------------------------------------------------------
// Bucket scatter: one pass, no count, no scan.
//   slots[f*CAP + pos] = (to, e)
// ---------------------------------------------------------------------------
__global__ void scatter_k(const int* __restrict__ ei, int* __restrict__ deg,
                          int2* __restrict__ slots) {
    int e = blockIdx.x * blockDim.x + threadIdx.x;
    if (e < NE) {
        int f  = ei[2 * e];
        int to = ei[2 * e + 1];
        int p = atomicAdd(&deg[f], 1);
        if (p < CAP) slots[(size_t)f * CAP + p] = make_int2(to, e);
    }
}

// ---------------------------------------------------------------------------
// Fused GEMM: C[m][n] = (sum_k X[m][k]*Wrow_n[k] + bias_n) * (EXISTS? ex[m]:1)
//   Wrow_n = W1 + n*ldw          for n < 128
//          = W2 + (n-128)*ldw    for n >= 128   (BN_T == 256)
//   bias_n from bias1 (n<128) / bias2 (n>=128), nullptr -> 0.
//   Optional store (row stride BN_T), optional per-channel max into
//   cmax1 (cols <128) / cmax2 (cols >=128).
// Tile: BM=64, BN_T in {128,256}, BK=16, 256 threads, 8 x (BN_T/32) per thread.
// Warp w owns rows w*8..w*8+7 (A-row smem reads are warp-uniform broadcasts).
// ---------------------------------------------------------------------------
#define BM 64
#define BKT 16

template<int BN_T, bool EXISTS, bool STORE, bool CMAX>
__global__ __launch_bounds__(256)
void gemm2_k(const float* __restrict__ X, int ldx,
             const float* __restrict__ W1, const float* __restrict__ W2, int ldw,
             const float* __restrict__ bias1, const float* __restrict__ bias2,
             const float* __restrict__ ex,
             float* __restrict__ C,
             unsigned* __restrict__ cmax1, unsigned* __restrict__ cmax2,
             int M, int K) {
    constexpr int CN = BN_T / 32;
    __shared__ float As[BKT][BM + 4];
    __shared__ float Bs[BKT][BN_T + 4];
    __shared__ unsigned smax[BN_T];

    const int tid  = threadIdx.x;
    const int warp = tid >> 5;
    const int lane = tid & 31;
    const int m0   = blockIdx.x * BM;
    const int colBase = lane * CN;

    if (CMAX) {
        for (int i = tid; i < BN_T; i += 256) smax[i] = ENC_NEG_INF;
    }

    float acc[8][CN];
#pragma unroll
    for (int i = 0; i < 8; i++)
#pragma unroll
        for (int j = 0; j < CN; j++) acc[i][j] = 0.f;

    for (int k0 = 0; k0 < K; k0 += BKT) {
        // A tile: 64 x 16 = 1024 elems, 4 per thread
#pragma unroll
        for (int i = 0; i < 4; i++) {
            int lin = tid + 256 * i;
            int mm = lin >> 4, kk = lin & 15;
            int gm = m0 + mm, gk = k0 + kk;
            As[kk][mm] = (gm < M && gk < K) ? X[(size_t)gm * ldx + gk] : 0.f;
        }
        // B tile: BN_T x 16 elems
#pragma unroll
        for (int i = 0; i < BN_T / 16; i++) {
            int lin = tid + 256 * i;
            int nn = lin >> 4, kk = lin & 15;
            int gk = k0 + kk;
            const float* wrow = (BN_T == 128 || nn < 128)
                                    ? (W1 + (size_t)nn * ldw)
                                    : (W2 + (size_t)(nn - 128) * ldw);
            Bs[kk][nn] = (gk < K) ? wrow[gk] : 0.f;
        }
        __syncthreads();

#pragma unroll
        for (int kk = 0; kk < BKT; kk++) {
            float a[8];
            *(float4*)&a[0] = *(const float4*)&As[kk][warp * 8];
            *(float4*)&a[4] = *(const float4*)&As[kk][warp * 8 + 4];
            float b[CN];
#pragma unroll
            for (int q = 0; q < CN; q += 4)
                *(float4*)&b[q] = *(const float4*)&Bs[kk][colBase + q];
#pragma unroll
            for (int i = 0; i < 8; i++)
#pragma unroll
                for (int j = 0; j < CN; j++)
                    acc[i][j] = fmaf(a[i], b[j], acc[i][j]);
        }
        __syncthreads();
    }

    // Epilogue
    float bv[CN];
#pragma unroll
    for (int j = 0; j < CN; j++) {
        int col = colBase + j;
        if (BN_T == 128 || col < 128)
            bv[j] = bias1 ? bias1[col] : 0.f;
        else
            bv[j] = bias2 ? bias2[col - 128] : 0.f;
    }

    unsigned cm[CN];
#pragma unroll
    for (int j = 0; j < CN; j++) cm[j] = ENC_NEG_INF;

#pragma unroll
    for (int i = 0; i < 8; i++) {
        int gm = m0 + warp * 8 + i;
        if (gm < M) {
            float e = EXISTS ? ex[gm] : 1.f;
            float v[CN];
#pragma unroll
            for (int j = 0; j < CN; j++) {
                v[j] = (acc[i][j] + bv[j]) * e;
                if (CMAX) cm[j] = max(cm[j], encf(v[j]));
            }
            if (STORE) {
#pragma unroll
                for (int q = 0; q < CN; q += 4)
                    *(float4*)&C[(size_t)gm * BN_T + colBase + q] =
                        make_float4(v[q], v[q + 1], v[q + 2], v[q + 3]);
            }
        }
    }

    if (CMAX) {
#pragma unroll
        for (int j = 0; j < CN; j++) atomicMax(&smax[colBase + j], cm[j]);
        __syncthreads();
        for (int i = tid; i < BN_T; i += 256) {
            unsigned* dst = (BN_T == 128 || i < 128) ? &cmax1[i] : &cmax2[i - 128];
            atomicMax(dst, smax[i]);
        }
    }
}

// ---------------------------------------------------------------------------
// Segmented max per node (warp per node, 4 channels per lane):
//   M[h]      = max_{e: from=n} (B[to_e][h] + edge_b[h] + ef[e] . W3[h])
//   cf_new[n] = relu(A[n] + M)   (0 if degree 0)
// A at AB[n*256 + c], B rows at AB[to*256 + 128 + c].
// Also accumulates per-channel max over nodes (pmax).
// ---------------------------------------------------------------------------
__global__ __launch_bounds__(256)
void segmax_k(const float* __restrict__ AB,
              const int2* __restrict__ slots, const int* __restrict__ deg,
              const float* __restrict__ ef,
              const float* __restrict__ Wit,   // edge_w + iter*128*260
              const float* __restrict__ bit,   // edge_b + iter*128
              float* __restrict__ cfo, unsigned* __restrict__ pmax) {
    __shared__ unsigned smax[H_DIM];
    const int tid = threadIdx.x;
    if (tid < H_DIM) smax[tid] = ENC_NEG_INF;
    __syncthreads();

    const int warp = tid >> 5, lane = tid & 31;
    const int n = blockIdx.x * (blockDim.x >> 5) + warp;   // exact grid: always < NN
    const int c0 = lane * 4;

    float w3[4][4], bb[4];
#pragma unroll
    for (int j = 0; j < 4; j++) {
        bb[j] = bit[c0 + j];
#pragma unroll
        for (int q = 0; q < 4; q++)
            w3[j][q] = Wit[(size_t)(c0 + j) * EW_LD + 256 + q];
    }

    float4 m = make_float4(-1e30f, -1e30f, -1e30f, -1e30f);
    const int d = min(deg[n], CAP);
    const int2* sl = slots + (size_t)n * CAP;
    for (int p = 0; p < d; p++) {
        int2 te = sl[p];
        float4 bv = *(const float4*)(AB + (size_t)te.x * 256 + 128 + c0);
        float4 e4 = *(const float4*)(ef + (size_t)te.y * 4);
        float cx = bv.x + bb[0] + e4.x*w3[0][0] + e4.y*w3[0][1] + e4.z*w3[0][2] + e4.w*w3[0][3];
        float cy = bv.y + bb[1] + e4.x*w3[1][0] + e4.y*w3[1][1] + e4.z*w3[1][2] + e4.w*w3[1][3];
        float cz = bv.z + bb[2] + e4.x*w3[2][0] + e4.y*w3[2][1] + e4.z*w3[2][2] + e4.w*w3[2][3];
        float cw = bv.w + bb[3] + e4.x*w3[3][0] + e4.y*w3[3][1] + e4.z*w3[3][2] + e4.w*w3[3][3];
        m.x = fmaxf(m.x, cx); m.y = fmaxf(m.y, cy);
        m.z = fmaxf(m.z, cz); m.w = fmaxf(m.w, cw);
    }

    float4 a = *(const float4*)(AB + (size_t)n * 256 + c0);
    float4 o;
    if (d > 0) {
        o.x = fmaxf(0.f, a.x + m.x);
        o.y = fmaxf(0.f, a.y + m.y);
        o.z = fmaxf(0.f, a.z + m.z);
        o.w = fmaxf(0.f, a.w + m.w);
    } else {
        o = make_float4(0.f, 0.f, 0.f, 0.f);
    }
    *(float4*)(cfo + (size_t)n * H_DIM + c0) = o;

    atomicMax(&smax[c0 + 0], encf(o.x));
    atomicMax(&smax[c0 + 1], encf(o.y));
    atomicMax(&smax[c0 + 2], encf(o.z));
    atomicMax(&smax[c0 + 3], encf(o.w));
    __syncthreads();
    if (tid < H_DIM) atomicMax(&pmax[tid], smax[tid]);
}

// ---------------------------------------------------------------------------
// Final heads: parent_feat GEMV (384->128) + geo head (GEMV + group-norm)
// One block, 128 threads.
// ---------------------------------------------------------------------------
__global__ __launch_bounds__(128)
void final_k(const unsigned* __restrict__ p0, const unsigned* __restrict__ p1,
             const unsigned* __restrict__ p2,
             const float* __restrict__ second_w, const float* __restrict__ second_b,
             const unsigned* __restrict__ gcg, const unsigned* __restrict__ gskip,
             const float* __restrict__ sgw, const float* __restrict__ sgb,
             const float* __restrict__ gnw, const float* __restrict__ gnb,
             float* __restrict__ out) {
    __shared__ float pf[384];
    __shared__ float pg[H_DIM];
    __shared__ float sg[H_DIM];
    __shared__ float gv[H_DIM];
    const int t = threadIdx.x;

    pf[t]       = decf(p0[t]);
    pf[128 + t] = decf(p1[t]);
    pf[256 + t] = decf(p2[t]);
    pg[t] = leaky(decf(gcg[t]));
    sg[t] = leaky(decf(gskip[t]));
    __syncthreads();

    // parent_feat
    float acc = second_b[t];
    const float* wr = second_w + (size_t)t * 384;
#pragma unroll 8
    for (int k = 0; k < 384; k++) acc = fmaf(pf[k], wr[k], acc);
    out[t] = leaky(acc);

    // geo GEMV
    float g = sgb[t];
    const float* gr = sgw + (size_t)t * H_DIM;
#pragma unroll 8
    for (int k = 0; k < H_DIM; k++) g = fmaf(pg[k], gr[k], g);
    gv[t] = g;
    __syncthreads();

    // group norm: 16 groups of 8
    const float* gp = &gv[(t >> 3) << 3];
    float mu = 0.f;
#pragma unroll
    for (int i = 0; i < 8; i++) mu += gp[i];
    mu *= 0.125f;
    float var = 0.f;
#pragma unroll
    for (int i = 0; i < 8; i++) { float dd = gp[i] - mu; var += dd * dd; }
    var *= 0.125f;
    float xn = (gv[t] - mu) * rsqrtf(var + 1e-5f);
    float y = xn * gnw[t] + gnb[t];
    out[128 + t] = leaky(sg[t] + y);
}

// ---------------------------------------------------------------------------
// Launch
// ---------------------------------------------------------------------------
extern "C" void kernel_launch(void* const* d_in, const int* in_sizes, int n_in,
                              void* d_out, int out_size) {
    const float* child_feats   = (const float*)d_in[0];
    const float* child_geo     = (const float*)d_in[1];
    const float* child_exists  = (const float*)d_in[2];
    const float* edge_onehot   = (const float*)d_in[3];
    const int*   edge_indices  = (const int*)  d_in[4];
    const float* child_op_w    = (const float*)d_in[5];
    const float* child_op_b    = (const float*)d_in[6];
    const float* second_w      = (const float*)d_in[7];
    const float* second_b      = (const float*)d_in[8];
    const float* edge_w        = (const float*)d_in[9];
    const float* edge_b        = (const float*)d_in[10];
    const float* child_geo_w   = (const float*)d_in[11];
    const float* child_geo_b   = (const float*)d_in[12];
    const float* second_geo_w  = (const float*)d_in[13];
    const float* second_geo_b  = (const float*)d_in[14];
    const float* gn_w          = (const float*)d_in[15];
    const float* gn_b          = (const float*)d_in[16];
    const float* skip_w        = (const float*)d_in[17];
    const float* skip_b        = (const float*)d_in[18];
    float* out = (float*)d_out;

    float *cf0, *cf1, *AB;
    int *deg;
    int2* slots;
    unsigned *p0, *p1, *p2, *gcg, *gskip;
    cudaGetSymbolAddress((void**)&cf0,   g_cf0);
    cudaGetSymbolAddress((void**)&cf1,   g_cf1);
    cudaGetSymbolAddress((void**)&AB,    g_AB);
    cudaGetSymbolAddress((void**)&deg,   g_deg);
    cudaGetSymbolAddress((void**)&slots, g_slots);
    cudaGetSymbolAddress((void**)&p0,    g_p0);
    cudaGetSymbolAddress((void**)&p1,    g_p1);
    cudaGetSymbolAddress((void**)&p2,    g_p2);
    cudaGetSymbolAddress((void**)&gcg,   g_gcg);
    cudaGetSymbolAddress((void**)&gskip, g_gskip);

    const int gemm_grid = (NN + BM - 1) / BM;   // 313
    const int seg_grid  = NN / 8;               // 2500 (8 warps/block, exact)

    init_k<<<(NN + 255) / 256, 256>>>(deg, p0, p1, p2, gcg, gskip);

    // Grouping by idx_from: single-pass bucket scatter (no count, no scan)
    scatter_k<<<(NE + 255) / 256, 256>>>(edge_indices, deg, slots);

    // cf0 = (child_feats @ Wop^T + b) * exists ; p0 = channel max
    gemm2_k<128, true, true, true><<<gemm_grid, 256>>>(
        child_feats, K_CF, child_op_w, nullptr, K_CF, child_op_b, nullptr,
        child_exists, cf0, p0, nullptr, NN, K_CF);

    // ---- iteration 0: fused A|B projection, then segmented max ----
    gemm2_k<256, false, true, false><<<gemm_grid, 256>>>(
        cf0, H_DIM, edge_w, edge_w + 128, EW_LD, nullptr, nullptr,
        nullptr, AB, nullptr, nullptr, NN, H_DIM);
    segmax_k<<<seg_grid, 256>>>(AB, slots, deg, edge_onehot,
                                edge_w, edge_b, cf1, p1);

    // ---- iteration 1 ----
    gemm2_k<256, false, true, false><<<gemm_grid, 256>>>(
        cf1, H_DIM, edge_w + EW_ITER_STRIDE, edge_w + EW_ITER_STRIDE + 128,
        EW_LD, nullptr, nullptr, nullptr, AB, nullptr, nullptr, NN, H_DIM);
    segmax_k<<<seg_grid, 256>>>(AB, slots, deg, edge_onehot,
                                edge_w + EW_ITER_STRIDE, edge_b + 128, cf0, p2);

    // ---- geo path: fused skip|cg projection, channel maxima only ----
    gemm2_k<256, true, false, true><<<gemm_grid, 256>>>(
        child_geo, FG_DIM, skip_w, child_geo_w, FG_DIM, skip_b, child_geo_b,
        child_exists, nullptr, gskip, gcg, NN, FG_DIM);

    // ---- heads ----
    final_k<<<1, 128>>>(p0, p1, p2, second_w, second_b, gcg, gskip,
                        second_geo_w, second_geo_b, gn_w, gn_b, out);
}